// round 3
// baseline (speedup 1.0000x reference)
#include <cuda_runtime.h>

#define NUM_OUTPUTS 1032
#define D4 258              // 1032 / 4 float4 chunks per row
#define MAX_ACTIVE 32
#define BATCH 4096
#define THREADS 256

__global__ __launch_bounds__(THREADS)
void ft_gather_kernel(const int*    __restrict__ idx,
                      const float*  __restrict__ vals,
                      const float4* __restrict__ W4,
                      const float4* __restrict__ bias4,
                      float4*       __restrict__ out4)
{
    const int row = blockIdx.x;
    const int tid = threadIdx.x;

    __shared__ int   sIdx[MAX_ACTIVE];
    __shared__ float sVal[MAX_ACTIVE];
    if (tid < MAX_ACTIVE) {
        sIdx[tid] = idx[row * MAX_ACTIVE + tid];
        sVal[tid] = vals[row * MAX_ACTIVE + tid];
    }
    __syncthreads();

    const int c0 = tid;
    const int c1 = tid + THREADS;          // only tid 0..1 valid (258 chunks)
    const bool has2 = (c1 < D4);

    float4 a0 = bias4[c0];
    float4 a1 = has2 ? bias4[c1] : make_float4(0.f, 0.f, 0.f, 0.f);

    #pragma unroll 4
    for (int k = 0; k < MAX_ACTIVE; ++k) {
        const float4* wr = W4 + (size_t)sIdx[k] * D4;
        const float v = sVal[k];
        float4 w0 = __ldg(wr + c0);
        a0.x = fmaf(w0.x, v, a0.x);
        a0.y = fmaf(w0.y, v, a0.y);
        a0.z = fmaf(w0.z, v, a0.z);
        a0.w = fmaf(w0.w, v, a0.w);
        if (has2) {
            float4 w1 = __ldg(wr + c1);
            a1.x = fmaf(w1.x, v, a1.x);
            a1.y = fmaf(w1.y, v, a1.y);
            a1.z = fmaf(w1.z, v, a1.z);
            a1.w = fmaf(w1.w, v, a1.w);
        }
    }

    float4* orow = out4 + (size_t)row * D4;
    orow[c0] = a0;
    if (has2) orow[c1] = a1;
}

extern "C" void kernel_launch(void* const* d_in, const int* in_sizes, int n_in,
                              void* d_out, int out_size)
{
    // metadata order:
    //   0: feature_indices_0  int32  [4096, 32]
    //   1: feature_values_0   f32    [4096, 32]
    //   2: feature_indices_1  int32  [4096, 32]
    //   3: feature_values_1   f32    [4096, 32]
    //   4: merged_weight      f32    [45056, 1032]
    //   5: bias               f32    [1032]
    const int*    idx0 = (const int*)   d_in[0];
    const float*  val0 = (const float*) d_in[1];
    const int*    idx1 = (const int*)   d_in[2];
    const float*  val1 = (const float*) d_in[3];
    const float4* W4   = (const float4*)d_in[4];
    const float4* b4   = (const float4*)d_in[5];

    float4* out0 = (float4*)d_out;                                   // [4096, 1032]
    float4* out1 = (float4*)((float*)d_out + (size_t)BATCH * NUM_OUTPUTS);

    ft_gather_kernel<<<BATCH, THREADS>>>(idx0, val0, W4, b4, out0);
    ft_gather_kernel<<<BATCH, THREADS>>>(idx1, val1, W4, b4, out1);
}

// round 4
// speedup vs baseline: 1.6900x; 1.6900x over previous
#include <cuda_runtime.h>

#define NUM_OUTPUTS 1032
#define D4 258              // 1032 floats = 258 float4 per weight row
#define CHUNK 86            // float4 per column chunk (3 chunks: 86*3 = 258)
#define NCHUNK 3
#define MAX_ACTIVE 32
#define BATCH 4096
#define THREADS 96          // 3 warps; lanes 0..85 active

__global__ __launch_bounds__(THREADS)
void ft_chunk_kernel(const int*    __restrict__ idx0,
                     const float*  __restrict__ val0,
                     const int*    __restrict__ idx1,
                     const float*  __restrict__ val1,
                     const float4* __restrict__ W4,
                     const float4* __restrict__ bias4,
                     float4*       __restrict__ out4)
{
    const int r     = blockIdx.x;          // 0..8191 : both feature sets fused
    const int chunk = blockIdx.y;          // 0..2    : slow scheduling dim -> phases
    const int tid   = threadIdx.x;

    const int*   idx;
    const float* val;
    int row;
    if (r < BATCH) { idx = idx0; val = val0; row = r; }
    else           { idx = idx1; val = val1; row = r - BATCH; }

    __shared__ int   sIdx[MAX_ACTIVE];
    __shared__ float sVal[MAX_ACTIVE];
    if (tid < MAX_ACTIVE) {
        sIdx[tid] = idx[row * MAX_ACTIVE + tid];
        sVal[tid] = val[row * MAX_ACTIVE + tid];
    }
    __syncthreads();

    if (tid >= CHUNK) return;              // no further barriers below

    const int c = chunk * CHUNK + tid;     // float4 column index, 0..257

    float4 a = bias4[c];

    #pragma unroll 4
    for (int k = 0; k < MAX_ACTIVE; ++k) {
        const float4 w = __ldg(W4 + (size_t)sIdx[k] * D4 + c);
        const float  v = sVal[k];
        a.x = fmaf(w.x, v, a.x);
        a.y = fmaf(w.y, v, a.y);
        a.z = fmaf(w.z, v, a.z);
        a.w = fmaf(w.w, v, a.w);
    }

    // out rows 0..4095 = out0, 4096..8191 = out1 (contiguous in d_out)
    out4[(size_t)r * D4 + c] = a;
}

extern "C" void kernel_launch(void* const* d_in, const int* in_sizes, int n_in,
                              void* d_out, int out_size)
{
    // metadata order:
    //   0: feature_indices_0  int32  [4096, 32]
    //   1: feature_values_0   f32    [4096, 32]
    //   2: feature_indices_1  int32  [4096, 32]
    //   3: feature_values_1   f32    [4096, 32]
    //   4: merged_weight      f32    [45056, 1032]
    //   5: bias               f32    [1032]
    const int*    idx0 = (const int*)   d_in[0];
    const float*  val0 = (const float*) d_in[1];
    const int*    idx1 = (const int*)   d_in[2];
    const float*  val1 = (const float*) d_in[3];
    const float4* W4   = (const float4*)d_in[4];
    const float4* b4   = (const float4*)d_in[5];

    float4* out = (float4*)d_out;   // [8192, 1032] : out0 then out1

    dim3 grid(2 * BATCH, NCHUNK);
    ft_chunk_kernel<<<grid, THREADS>>>(idx0, val0, idx1, val1, W4, b4, out);
}